// round 6
// baseline (speedup 1.0000x reference)
#include <cuda_runtime.h>
#include <cuda_bf16.h>
#include <float.h>

// FiltrationLayer: per row of 4096 fp32, pivot = 2nd-largest value,
// out = 1.0f where x >= pivot else 0.0f.
//
// R5 (resubmit after container flake): persistent CTAs + cross-row software
// pipelining. Each CTA owns ~44 rows (grid-stride). While reducing/storing
// row r, the 16 LDG.128 for row r+stride are already in flight -> no
// memory-idle bubble during the reduce phase or at CTA retire.

#define ROW_LEN 4096
#define THREADS 256
#define VEC_PER_THREAD 4   // 4 x float4 = 16 floats/thread
#define NUM_SMS 148
#define CTAS_PER_SM 5

__device__ __forceinline__ void merge_val(float x, float& t1, float& t2) {
    float hi = fmaxf(t1, x);
    float lo = fminf(t1, x);
    t2 = fmaxf(t2, lo);
    t1 = hi;
}

__device__ __forceinline__ void merge_pair(float b1, float b2, float& t1, float& t2) {
    float hi = fmaxf(t1, b1);
    float lo = fminf(t1, b1);
    t2 = fmaxf(fmaxf(t2, b2), lo);
    t1 = hi;
}

__device__ __forceinline__ float sel01(float x, float pivot) {
    unsigned m = (unsigned)-(int)(x >= pivot);
    return __uint_as_float(0x3f800000u & m);
}

__global__ __launch_bounds__(THREADS, CTAS_PER_SM)
void filtration_top2_persistent(const float* __restrict__ in,
                                float* __restrict__ out, int rows) {
    const int t = threadIdx.x;
    const int warp = t >> 5;
    const int lane = t & 31;
    const long long stride = gridDim.x;

    __shared__ float s1[THREADS / 32], s2[THREADS / 32];

    long long r = blockIdx.x;
    if (r >= rows) return;

    // Preload first row
    float4 v[VEC_PER_THREAD];
    {
        const float4* __restrict__ inp = reinterpret_cast<const float4*>(in + r * ROW_LEN);
#pragma unroll
        for (int k = 0; k < VEC_PER_THREAD; k++)
            v[k] = inp[t + k * THREADS];
    }

    while (true) {
        const long long rn = r + stride;
        const bool has_next = (rn < rows);

        // Prefetch next row — independent of everything below, so these 4
        // LDG.128 stay in flight across the whole reduce+store of row r.
        float4 w[VEC_PER_THREAD];
        if (has_next) {
            const float4* __restrict__ inp2 = reinterpret_cast<const float4*>(in + rn * ROW_LEN);
#pragma unroll
            for (int k = 0; k < VEC_PER_THREAD; k++)
                w[k] = inp2[t + k * THREADS];
        }

        // Local top-2 of current row
        float t1 = -FLT_MAX, t2 = -FLT_MAX;
#pragma unroll
        for (int k = 0; k < VEC_PER_THREAD; k++) {
            merge_val(v[k].x, t1, t2);
            merge_val(v[k].y, t1, t2);
            merge_val(v[k].z, t1, t2);
            merge_val(v[k].w, t1, t2);
        }

        // Warp reduce
#pragma unroll
        for (int off = 16; off > 0; off >>= 1) {
            float o1 = __shfl_xor_sync(0xFFFFFFFFu, t1, off);
            float o2 = __shfl_xor_sync(0xFFFFFFFFu, t2, off);
            merge_pair(o1, o2, t1, t2);
        }

        // Cross-warp reduce via smem (reused every iteration -> barrier both sides)
        if (lane == 0) { s1[warp] = t1; s2[warp] = t2; }
        __syncthreads();

        float r1 = -FLT_MAX, r2 = -FLT_MAX;
#pragma unroll
        for (int w8 = 0; w8 < THREADS / 32; w8++)
            merge_pair(s1[w8], s2[w8], r1, r2);

        const float pivot = r2;  // 2nd largest in the row
        __syncthreads();         // protect s1/s2 before next iteration's writes

        // Store binary output for row r
        {
            float4* __restrict__ outp = reinterpret_cast<float4*>(out + r * ROW_LEN);
#pragma unroll
            for (int k = 0; k < VEC_PER_THREAD; k++) {
                float4 o;
                o.x = sel01(v[k].x, pivot);
                o.y = sel01(v[k].y, pivot);
                o.z = sel01(v[k].z, pivot);
                o.w = sel01(v[k].w, pivot);
                outp[t + k * THREADS] = o;
            }
        }

        if (!has_next) break;
#pragma unroll
        for (int k = 0; k < VEC_PER_THREAD; k++) v[k] = w[k];
        r = rn;
    }
}

extern "C" void kernel_launch(void* const* d_in, const int* in_sizes, int n_in,
                              void* d_out, int out_size) {
    const float* in = (const float*)d_in[0];
    float* out = (float*)d_out;
    const int n = in_sizes[0];
    const int rows = n / ROW_LEN;  // 32768
    int grid = NUM_SMS * CTAS_PER_SM;  // 740 persistent CTAs
    if (grid > rows) grid = rows;
    filtration_top2_persistent<<<grid, THREADS>>>(in, out, rows);
}